// round 6
// baseline (speedup 1.0000x reference)
#include <cuda_runtime.h>

// DeepSeek-V3 grouped top-k router, round 5.
// Two tokens per warp processed in LOCKSTEP (interleaved extraction rounds
// for 2x ILP on the serial REDUX/shfl chains). Exact u64 sort keys; all
// tie-breaks bit-exact vs jax.lax.top_k.

#define FULL  0xFFFFFFFFu
#define TOPK  8
#define SCALE 2.5f

__device__ __forceinline__ unsigned f2ord(float f) {
    unsigned u = __float_as_uint(f);
    return u ^ (unsigned)(((int)u >> 31) | 0x80000000);   // monotonic f32->u32
}
__device__ __forceinline__ float ord2f(unsigned v) {
    return __uint_as_float((v & 0x80000000u) ? (v ^ 0x80000000u) : ~v);
}

// descending compare-exchange on u64 keys
#define CE(k, i, j)                                           \
    {                                                         \
        unsigned long long _a = k[i], _b = k[j];              \
        bool _p = _a < _b;                                    \
        k[i] = _p ? _b : _a;                                  \
        k[j] = _p ? _a : _b;                                  \
    }

// Batcher odd-even mergesort of 8, descending, 19 CEs
#define SORT8(k)                                              \
    CE(k,0,1) CE(k,2,3) CE(k,4,5) CE(k,6,7)                   \
    CE(k,0,2) CE(k,1,3) CE(k,4,6) CE(k,5,7)                   \
    CE(k,1,2) CE(k,5,6)                                       \
    CE(k,0,4) CE(k,1,5) CE(k,2,6) CE(k,3,7)                   \
    CE(k,2,4) CE(k,3,5)                                       \
    CE(k,1,2) CE(k,3,4) CE(k,5,6)

__device__ __forceinline__ void pack_keys(unsigned long long* k,
                                          const float4& a, const float4& b,
                                          const float4& ba, const float4& bb)
{
    // key = (ordered biased score << 32) | (slot ^ 7)   (7-s == s^7 for 3 bits)
    k[0] = ((unsigned long long)f2ord(a.x + ba.x) << 32) | 7u;
    k[1] = ((unsigned long long)f2ord(a.y + ba.y) << 32) | 6u;
    k[2] = ((unsigned long long)f2ord(a.z + ba.z) << 32) | 5u;
    k[3] = ((unsigned long long)f2ord(a.w + ba.w) << 32) | 4u;
    k[4] = ((unsigned long long)f2ord(b.x + bb.x) << 32) | 3u;
    k[5] = ((unsigned long long)f2ord(b.y + bb.y) << 32) | 2u;
    k[6] = ((unsigned long long)f2ord(b.z + bb.z) << 32) | 1u;
    k[7] = ((unsigned long long)f2ord(b.w + bb.w) << 32) | 0u;
}

// group top-2 sum + distributed rank: lane 4g+j checks groups {j, j+4}.
__device__ __forceinline__ bool group_dead(const unsigned long long* k,
                                           int j, bool c0, bool c1)
{
    float m1 = ord2f((unsigned)(k[0] >> 32));
    float m2 = ord2f((unsigned)(k[1] >> 32));
    #pragma unroll
    for (int off = 1; off < 4; off <<= 1) {
        float o1 = __shfl_xor_sync(FULL, m1, off);
        float o2 = __shfl_xor_sync(FULL, m2, off);
        float n2 = fmaxf(fminf(m1, o1), (m1 >= o1) ? m2 : o2);
        m1 = fmaxf(m1, o1);
        m2 = n2;
    }
    const float gs  = m1 + m2;
    const float gh0 = __shfl_sync(FULL, gs, j << 2);
    const float gh1 = __shfl_sync(FULL, gs, (j + 4) << 2);
    int part = (int)((gh0 > gs) || (gh0 == gs && c0))
             + (int)((gh1 > gs) || (gh1 == gs && c1));
    part += __shfl_xor_sync(FULL, part, 1);
    part += __shfl_xor_sync(FULL, part, 2);
    return part >= 4;     // rank among 8 groups (ties -> lower group wins)
}

// one warp-argmax extraction round (REDUX + ballot; lowest lane wins ties)
#define EXTRACT(k, p0, p1, it)                                           \
    {                                                                    \
        unsigned hk  = (unsigned)(k[0] >> 32);                           \
        unsigned m   = __reduce_max_sync(FULL, hk);                      \
        unsigned bal = __ballot_sync(FULL, hk == m);                     \
        int wl       = __ffs(bal) - 1;                                   \
        unsigned lo  = __shfl_sync(FULL, (unsigned)k[0], wl);            \
        unsigned id  = ((unsigned)wl << 3) + ((lo ^ 7u) & 7u);           \
        if ((it) < 4) p0 = __byte_perm(p0, id, sel[(it)]);               \
        else          p1 = __byte_perm(p1, id, sel[(it)-4]);             \
        bool amw = (lane == wl);                                         \
        _Pragma("unroll")                                                \
        for (int d = 0; d < 7 - (it); d++)                               \
            if (amw) k[d] = k[d + 1];                                    \
    }

__global__ __launch_bounds__(128, 9)
void topk_router_kernel(const float* __restrict__ logits,
                        const float* __restrict__ bias,
                        float* __restrict__ out_w,
                        float* __restrict__ out_id,
                        int T)
{
    const int gwarp = (blockIdx.x * blockDim.x + threadIdx.x) >> 5;
    const int lane  = threadIdx.x & 31;
    const int g     = lane >> 2;
    const int j     = lane & 3;
    const bool c0   = j < g;
    const bool c1   = (j + 4) < g;

    const int t0 = gwarp * 2;
    if (t0 >= T) return;
    const int  t1   = (t0 + 1 < T) ? t0 + 1 : t0;
    const bool pair = (t1 == t0 + 1);

    const float* rowA = logits + (size_t)t0 * 256;
    const float* rowB = logits + (size_t)t1 * 256;

    // all 6 LDG.128 issued up front: memory latency overlaps key packing
    const float4 ba = __ldg(reinterpret_cast<const float4*>(bias + lane * 8));
    const float4 bb = __ldg(reinterpret_cast<const float4*>(bias + lane * 8 + 4));
    const float4 aA = __ldg(reinterpret_cast<const float4*>(rowA + lane * 8));
    const float4 bA = __ldg(reinterpret_cast<const float4*>(rowA + lane * 8 + 4));
    const float4 aB = __ldg(reinterpret_cast<const float4*>(rowB + lane * 8));
    const float4 bB = __ldg(reinterpret_cast<const float4*>(rowB + lane * 8 + 4));

    unsigned long long kA[8], kB[8];
    pack_keys(kA, aA, bA, ba, bb);
    pack_keys(kB, aB, bB, ba, bb);
    SORT8(kA)
    SORT8(kB)

    const bool deadA = group_dead(kA, j, c0, c1);
    const bool deadB = group_dead(kB, j, c0, c1);
    // dead lanes can never win: ord of any finite score > 0
    if (deadA) kA[0] &= 0xFFFFFFFFull;
    if (deadB) kB[0] &= 0xFFFFFFFFull;

    const unsigned sel[4] = {0x3214u, 0x3240u, 0x3410u, 0x4210u};
    unsigned pA0 = 0, pA1 = 0, pB0 = 0, pB1 = 0;
    #pragma unroll
    for (int it = 0; it < TOPK; it++) {
        EXTRACT(kA, pA0, pA1, it)      // A and B rounds are independent:
        EXTRACT(kB, pB0, pB1, it)      // 2x ILP on the REDUX/shfl chains
    }

    // lanes 0-7 finish token A, lanes 8-15 token B (one 64B coalesced store)
    const unsigned q0  = (lane < 8) ? pA0 : pB0;
    const unsigned q1  = (lane < 8) ? pA1 : pB1;
    const unsigned pk  = ((lane & 7) < 4) ? q0 : q1;
    const unsigned myid = (pk >> ((lane & 3) * 8)) & 255u;
    const float* row = (lane < 8) ? rowA : rowB;

    float w = 0.0f;
    if (lane < 16) w = __ldg(row + myid);      // L1-hot exact unbiased logit
    float wsum = w;                            // sum within each 8-lane half
    wsum += __shfl_xor_sync(FULL, wsum, 1);
    wsum += __shfl_xor_sync(FULL, wsum, 2);
    wsum += __shfl_xor_sync(FULL, wsum, 4);
    const float inv = __fdividef(SCALE, wsum);

    if (pair) {
        if (lane < 16) {
            size_t o = (size_t)t0 * TOPK + lane;   // contiguous 16 floats
            out_w[o]  = w * inv;
            out_id[o] = (float)myid;
        }
    } else {
        if (lane < 8) {
            size_t o = (size_t)t0 * TOPK + lane;
            out_w[o]  = w * inv;
            out_id[o] = (float)myid;
        }
    }
}

extern "C" void kernel_launch(void* const* d_in, const int* in_sizes, int n_in,
                              void* d_out, int out_size)
{
    const float* logits = (const float*)d_in[0];
    const float* bias   = (const float*)d_in[1];
    const int T = in_sizes[0] / 256;

    float* out_w  = (float*)d_out;
    float* out_id = out_w + (size_t)T * TOPK;   // [weights | ids] halves

    const int threads = 128;                    // 4 warps x 2 tokens
    const int tokens_per_block = (threads / 32) * 2;
    const int blocks = (T + tokens_per_block - 1) / tokens_per_block;
    topk_router_kernel<<<blocks, threads>>>(logits, bias, out_w, out_id, T);
}

// round 7
// speedup vs baseline: 1.3568x; 1.3568x over previous
#include <cuda_runtime.h>

// DeepSeek-V3 grouped top-k router, round 6.
// Warp = 2 tokens. Group scoring via cheap f32 top-2 scan, then SHUFFLE
// COMPACTION: token A's 4 alive groups -> lanes 0-15, token B's -> 16-31.
// The expensive u64 sort + 8 extraction rounds then run ONCE per warp for
// both tokens. All tie-breaks bit-exact vs jax.lax.top_k.

#define FULL  0xFFFFFFFFu
#define TOPK  8
#define SCALE 2.5f

__device__ __forceinline__ unsigned f2ord(float f) {
    unsigned u = __float_as_uint(f);
    return u ^ (unsigned)(((int)u >> 31) | 0x80000000);   // monotonic f32->u32
}

// descending compare-exchange on u64 keys
#define CE(i, j)                                              \
    {                                                         \
        unsigned long long _a = k[i], _b = k[j];              \
        bool _p = _a < _b;                                    \
        k[i] = _p ? _b : _a;                                  \
        k[j] = _p ? _a : _b;                                  \
    }

// per-token: exact group top-2 sum, rank among 8 groups, alive ballot.
// gs uses VALUES only (ties irrelevant for a sum) -> f32 FMNMX scan is exact.
__device__ __forceinline__ unsigned alive_ballot(const float* s, int g, int j)
{
    float m1 = s[0];
    float m2 = __int_as_float(0xff800000);     // -inf
    #pragma unroll
    for (int e = 1; e < 8; e++) {
        float t = fminf(m1, s[e]);
        m1 = fmaxf(m1, s[e]);
        m2 = fmaxf(m2, t);
    }
    #pragma unroll
    for (int off = 1; off < 4; off <<= 1) {    // merge 4 lanes of the group
        float o1 = __shfl_xor_sync(FULL, m1, off);
        float o2 = __shfl_xor_sync(FULL, m2, off);
        float n2 = fmaxf(fminf(m1, o1), (m1 >= o1) ? m2 : o2);
        m1 = fmaxf(m1, o1);
        m2 = n2;
    }
    const float gs = m1 + m2;
    // distributed rank: lane 4g+j checks groups j and j+4 (ties -> lower grp)
    const float gh0 = __shfl_sync(FULL, gs, j << 2);
    const float gh1 = __shfl_sync(FULL, gs, (j + 4) << 2);
    int part = (int)((gh0 > gs) || (gh0 == gs && j < g))
             + (int)((gh1 > gs) || (gh1 == gs && (j + 4) < g));
    part += __shfl_xor_sync(FULL, part, 1);
    part += __shfl_xor_sync(FULL, part, 2);
    return __ballot_sync(FULL, part < 4);      // exactly 4 groups alive
}

__global__ __launch_bounds__(128)
void topk_router_kernel(const float* __restrict__ logits,
                        const float* __restrict__ bias,
                        float* __restrict__ out_w,
                        float* __restrict__ out_id,
                        int T)
{
    const int gwarp = (blockIdx.x * blockDim.x + threadIdx.x) >> 5;
    const int lane  = threadIdx.x & 31;
    const int g     = lane >> 2;
    const int j     = lane & 3;

    const int t0 = gwarp * 2;
    if (t0 >= T) return;
    const bool pair = (t0 + 1 < T);
    const int  t1   = pair ? t0 + 1 : t0;

    const float* rowA = logits + (size_t)t0 * 256;
    const float* rowB = logits + (size_t)t1 * 256;

    // all LDG.128 up front; latency overlaps the scoring phase
    const float4 ba = __ldg(reinterpret_cast<const float4*>(bias + lane * 8));
    const float4 bb = __ldg(reinterpret_cast<const float4*>(bias + lane * 8 + 4));
    const float4 aA = __ldg(reinterpret_cast<const float4*>(rowA + lane * 8));
    const float4 bA = __ldg(reinterpret_cast<const float4*>(rowA + lane * 8 + 4));
    const float4 aB = __ldg(reinterpret_cast<const float4*>(rowB + lane * 8));
    const float4 bB = __ldg(reinterpret_cast<const float4*>(rowB + lane * 8 + 4));

    float sA[8] = {aA.x + ba.x, aA.y + ba.y, aA.z + ba.z, aA.w + ba.w,
                   bA.x + bb.x, bA.y + bb.y, bA.z + bb.z, bA.w + bb.w};
    float sB[8] = {aB.x + ba.x, aB.y + ba.y, aB.z + ba.z, aB.w + ba.w,
                   bB.x + bb.x, bB.y + bb.y, bB.z + bb.z, bB.w + bb.w};

    const unsigned balA = alive_ballot(sA, g, j);
    const unsigned balB = alive_ballot(sB, g, j);

    // ---- compaction: lanes 0-15 take token A's alive groups, 16-31 B's ----
    const bool halfB = lane >= 16;
    const unsigned bal = halfB ? balB : balA;
    const unsigned gb  = bal & 0x11111111u;        // one bit per alive group
    const int ai = (lane >> 2) & 3;                // which alive group I want
    const unsigned x1 = gb & (gb - 1);             // clear lowest set bits
    const unsigned x2 = x1 & (x1 - 1);
    const unsigned x3 = x2 & (x2 - 1);
    unsigned pick = (ai == 0) ? gb : (ai == 1) ? x1 : (ai == 2) ? x2 : x3;
    const int src = (__ffs(pick) - 1) + j;         // source lane (0..31)

    // gather biased scores from source lane; pack exact u64 keys:
    // hi = ordered score, lo = (src<<3)|(slot^7)  ->  final id = lo^7
    unsigned long long k[8];
    const unsigned srcb = (unsigned)src << 3;
    #pragma unroll
    for (int e = 0; e < 8; e++) {
        float fA = __shfl_sync(FULL, sA[e], src);
        float fB = __shfl_sync(FULL, sB[e], src);
        float f  = halfB ? fB : fA;
        k[e] = ((unsigned long long)f2ord(f) << 32)
             | (unsigned long long)(srcb | (unsigned)(e ^ 7));
    }

    // ---- Batcher odd-even mergesort of 8, descending (once per warp) ----
    CE(0,1) CE(2,3) CE(4,5) CE(6,7)
    CE(0,2) CE(1,3) CE(4,6) CE(5,7)
    CE(1,2) CE(5,6)
    CE(0,4) CE(1,5) CE(2,6) CE(3,7)
    CE(2,4) CE(3,5)
    CE(1,2) CE(3,4) CE(5,6)

    // ---- 8 extraction rounds, both halves simultaneously ----
    const unsigned hm = halfB ? 0xFFFF0000u : 0x0000FFFFu;
    const unsigned sel[4] = {0x3214u, 0x3240u, 0x3410u, 0x4210u};
    unsigned p0 = 0, p1 = 0;
    #pragma unroll
    for (int it = 0; it < TOPK; it++) {
        unsigned hk = (unsigned)(k[0] >> 32);
        unsigned m  = hk;
        #pragma unroll
        for (int off = 1; off < 16; off <<= 1) {   // butterfly within half
            unsigned o = __shfl_xor_sync(FULL, m, off);
            m = (o > m) ? o : m;
        }
        unsigned blt = __ballot_sync(FULL, hk == m) & hm;
        int wl = __ffs(blt) - 1;                   // lowest lane = lowest id
        unsigned lo = __shfl_sync(FULL, (unsigned)k[0], wl);
        unsigned id = (lo ^ 7u) & 255u;            // src*8 + slot
        if (it < 4) p0 = __byte_perm(p0, id, sel[it]);
        else        p1 = __byte_perm(p1, id, sel[it - 4]);
        bool amw = (lane == wl);
        #pragma unroll
        for (int d = 0; d < 7 - it; d++)
            if (amw) k[d] = k[d + 1];
    }

    // ---- epilogue: lanes 0-7 emit token A, lanes 16-23 token B ----
    const int q = lane & 15;
    const unsigned pk   = (q < 4) ? p0 : p1;
    const unsigned myid = (pk >> ((lane & 3) * 8)) & 255u;
    const float* row = halfB ? rowB : rowA;

    float w = 0.0f;
    if (q < 8) w = __ldg(row + myid);              // exact unbiased logit, L1-hot
    float wsum = w;
    wsum += __shfl_xor_sync(FULL, wsum, 1);
    wsum += __shfl_xor_sync(FULL, wsum, 2);
    wsum += __shfl_xor_sync(FULL, wsum, 4);
    const float inv = __fdividef(SCALE, wsum);

    if ((q < 8) && (!halfB || pair)) {
        size_t o = (size_t)(halfB ? t1 : t0) * TOPK + q;
        out_w[o]  = w * inv;
        out_id[o] = (float)myid;
    }
}

extern "C" void kernel_launch(void* const* d_in, const int* in_sizes, int n_in,
                              void* d_out, int out_size)
{
    const float* logits = (const float*)d_in[0];
    const float* bias   = (const float*)d_in[1];
    const int T = in_sizes[0] / 256;

    float* out_w  = (float*)d_out;
    float* out_id = out_w + (size_t)T * TOPK;      // [weights | ids] halves

    const int threads = 128;                       // 4 warps x 2 tokens
    const int blocks  = (T + 7) / 8;
    topk_router_kernel<<<blocks, threads>>>(logits, bias, out_w, out_id, T);
}